// round 7
// baseline (speedup 1.0000x reference)
#include <cuda_runtime.h>
#include <cuda_fp16.h>

// ---------------------------------------------------------------------------
// MetaPath2Vec skip-gram loss — R7.
//
// Two fused launches only (so ncu's -s5-c1 window lands on a real kernel):
//   1) convert_zero_kernel : emb f32 -> fp16 table (128 MB) + zero g_acc
//   2) walk_fin_kernel     : gathers + loss, software-pipelined (double-
//                            buffered row gathers in registers), last-CTA
//                            finalize with self-resetting completion counter
//                            (deterministic under graph replay).
//
// Numerics (validated R3/R6): sig = 1/(1+expf(-x)) in f32, literal
// sig+1e-15f / 1-sig+1e-15f. fp16 table measured rel_err 1.27e-5.
// Indices are int32 on device.
// ---------------------------------------------------------------------------

#define N_EMB 500001
#define DIM   128

__device__ uint4    g_emb_h[(size_t)N_EMB * 16];  // fp16 table, 256 B/row
__device__ double   g_acc[2];                     // pos / neg term sums
__device__ unsigned g_done;                       // completion counter (wraps)

// ---------------- kernel 1: convert + zero ----------------
__global__ void __launch_bounds__(256)
convert_zero_kernel(const float* __restrict__ emb) {
    if (blockIdx.x == 0 && threadIdx.x < 2) g_acc[threadIdx.x] = 0.0;

    const size_t n_grp = (size_t)N_EMB * DIM / 8;   // 8000016 uint4 groups
    const float4* src = reinterpret_cast<const float4*>(emb);
    size_t i = (size_t)blockIdx.x * blockDim.x + threadIdx.x;
    const size_t stride = (size_t)gridDim.x * blockDim.x;
    for (; i < n_grp; i += stride) {
        float4 a = src[2 * i];
        float4 b = src[2 * i + 1];
        __half2 h0 = __floats2half2_rn(a.x, a.y);
        __half2 h1 = __floats2half2_rn(a.z, a.w);
        __half2 h2 = __floats2half2_rn(b.x, b.y);
        __half2 h3 = __floats2half2_rn(b.z, b.w);
        uint4 o;
        o.x = *reinterpret_cast<unsigned*>(&h0);
        o.y = *reinterpret_cast<unsigned*>(&h1);
        o.z = *reinterpret_cast<unsigned*>(&h2);
        o.w = *reinterpret_cast<unsigned*>(&h3);
        g_emb_h[i] = o;
    }
}

// ---------------- kernel 2: walk loss + finalize ----------------
__device__ __forceinline__ float warp_reduce_sum(float v) {
    v += __shfl_xor_sync(0xffffffffu, v, 16);
    v += __shfl_xor_sync(0xffffffffu, v, 8);
    v += __shfl_xor_sync(0xffffffffu, v, 4);
    v += __shfl_xor_sync(0xffffffffu, v, 2);
    v += __shfl_xor_sync(0xffffffffu, v, 1);
    return v;
}

__device__ __forceinline__ float dot4(uint2 a, uint2 b) {
    __half2 a0 = *reinterpret_cast<__half2*>(&a.x);
    __half2 a1 = *reinterpret_cast<__half2*>(&a.y);
    __half2 b0 = *reinterpret_cast<__half2*>(&b.x);
    __half2 b1 = *reinterpret_cast<__half2*>(&b.y);
    float2 fa0 = __half22float2(a0), fa1 = __half22float2(a1);
    float2 fb0 = __half22float2(b0), fb1 = __half22float2(b1);
    return fa0.x * fb0.x + fa0.y * fb0.y + fa1.x * fb1.x + fa1.y * fb1.y;
}

// load this lane's index slot for walk w (lanes 0..6 active)
__device__ __forceinline__ int load_idx(const int* __restrict__ pos_rw,
                                        const int* __restrict__ neg_rw,
                                        int w, int n_pos, int lane) {
    const int* rw = (w < n_pos) ? pos_rw + (size_t)w * 7
                                : neg_rw + (size_t)(w - n_pos) * 7;
    return (lane < 7) ? rw[lane] : 0;
}

__device__ __forceinline__ void issue_gather(int my, int lane, uint2* r) {
    const uint2* e = reinterpret_cast<const uint2*>(g_emb_h);
    #pragma unroll
    for (int k = 0; k < 7; k++) {
        int idx = __shfl_sync(0xffffffffu, my, k);
        r[k] = e[(size_t)idx * 32 + lane];
    }
}

__global__ void __launch_bounds__(256, 4)
walk_fin_kernel(const int* __restrict__ pos_rw,
                const int* __restrict__ neg_rw,
                int n_pos, int n_neg, float* __restrict__ out)
{
    __shared__ double sred[2][8];

    const int lane  = threadIdx.x & 31;
    const int wl    = threadIdx.x >> 5;
    const int gw    = (blockIdx.x * blockDim.x + threadIdx.x) >> 5;
    const int W     = (gridDim.x * blockDim.x) >> 5;
    const int total = n_pos + n_neg;

    double pos_acc = 0.0, neg_acc = 0.0;

    // prologue: indices + gathers for first walk
    int my = (gw < total) ? load_idx(pos_rw, neg_rw, gw, n_pos, lane) : 0;
    uint2 r[7];
    issue_gather(my, lane, r);

    for (int w = gw; w < total; w += W) {
        // ---- pipeline: fetch next walk's indices + issue its gathers ----
        int wn = w + W;
        int my_n = (wn < total) ? load_idx(pos_rw, neg_rw, wn, n_pos, lane) : 0;
        uint2 rn[7];
        issue_gather(my_n, lane, rn);   // in flight while we compute walk w

        // ---- compute walk w ----
        float d1 = dot4(r[0], r[1]);
        float d2 = dot4(r[0], r[2]);
        float d3 = dot4(r[0], r[3]);
        float d4 = dot4(r[0], r[4]);
        float d5 = dot4(r[0], r[5]);
        float d6 = dot4(r[0], r[6]);

        d1 = warp_reduce_sum(d1);
        d2 = warp_reduce_sum(d2);
        d3 = warp_reduce_sum(d3);
        d4 = warp_reduce_sum(d4);
        d5 = warp_reduce_sum(d5);
        d6 = warp_reduce_sum(d6);

        float dv = (lane == 0) ? d1 :
                   (lane == 1) ? d2 :
                   (lane == 2) ? d3 :
                   (lane == 3) ? d4 :
                   (lane == 4) ? d5 : d6;

        const bool is_pos = (w < n_pos);
        float sig  = 1.0f / (1.0f + expf(-dv));
        float arg  = is_pos ? (sig + 1e-15f) : (1.0f - sig + 1e-15f);
        float term = (lane < 6) ? (-logf(arg)) : 0.0f;

        term = warp_reduce_sum(term);
        if (lane == 0) {
            if (is_pos) pos_acc += (double)term;
            else        neg_acc += (double)term;
        }

        my = my_n;
        #pragma unroll
        for (int k = 0; k < 7; k++) r[k] = rn[k];
    }

    if (lane == 0) { sred[0][wl] = pos_acc; sred[1][wl] = neg_acc; }
    __syncthreads();

    if (threadIdx.x == 0) {
        double p = 0.0, n = 0.0;
        #pragma unroll
        for (int k = 0; k < 8; k++) { p += sred[0][k]; n += sred[1][k]; }
        atomicAdd(&g_acc[0], p);
        atomicAdd(&g_acc[1], n);
        __threadfence();
        // last CTA finalizes; atomicInc wraps to 0 -> deterministic replays
        unsigned ticket = atomicInc(&g_done, gridDim.x - 1);
        if (ticket == gridDim.x - 1) {
            double pos_loss = g_acc[0] / ((double)n_pos * 6.0);
            double neg_loss = g_acc[1] / ((double)n_neg * 6.0);
            out[0] = (float)(pos_loss + neg_loss);
        }
    }
}

extern "C" void kernel_launch(void* const* d_in, const int* in_sizes, int n_in,
                              void* d_out, int out_size)
{
    const float* emb    = (const float*)d_in[0];
    const int*   pos_rw = (const int*)d_in[1];
    const int*   neg_rw = (const int*)d_in[2];

    const int n_pos = in_sizes[1] / 7;   // 81920
    const int n_neg = in_sizes[2] / 7;   // 409600

    // 592 CTAs x 256 thr = 4736 warps (32/SM), ~104 walks per warp
    convert_zero_kernel<<<592, 256>>>(emb);
    walk_fin_kernel<<<592, 256>>>(pos_rw, neg_rw, n_pos, n_neg, (float*)d_out);
}

// round 8
// speedup vs baseline: 1.3510x; 1.3510x over previous
#include <cuda_runtime.h>
#include <cuda_fp16.h>

// ---------------------------------------------------------------------------
// MetaPath2Vec skip-gram loss — R8.
//
// R7 profile: walk kernel ISSUE-BOUND (issue=69.9%, fma=33%, alu=28.5%,
// L2 only 20.5%). ~200 issue slots/walk, dominated by 7 butterfly
// reductions (70), converts (28), slow expf/logf (~25).
//
// R8: ladder reduction (31 slots, ends with the 6 dot sums at lanes
// {0,4,8,16,20,24}), HFMA2 half2 dots (30), __expf/__frcp_rn/__logf
// (~10; __frcp_rn is IEEE-rounded so sig matches 1.0f/(1+e) bitwise,
// preserving the x=16.64 saturation cliff). Per-lane f32 term
// accumulators remove the term butterfly entirely.
//
// Numerics: fp16 table (R6: 1.27e-5) + fp16-accumulate dot noise ->
// predicted rel_err 2-4e-5, 25x under the 1e-3 gate.
// ---------------------------------------------------------------------------

#define N_EMB 500001
#define DIM   128

__device__ uint4    g_emb_h[(size_t)N_EMB * 16];  // fp16 table, 256 B/row
__device__ double   g_acc[2];                     // pos / neg term sums
__device__ unsigned g_done;                       // completion counter (wraps)

// ---------------- kernel 1: convert + zero ----------------
__global__ void __launch_bounds__(256)
convert_zero_kernel(const float* __restrict__ emb) {
    if (blockIdx.x == 0 && threadIdx.x < 2) g_acc[threadIdx.x] = 0.0;

    const size_t n_grp = (size_t)N_EMB * DIM / 8;   // 8000016 uint4 groups
    const float4* src = reinterpret_cast<const float4*>(emb);
    size_t i = (size_t)blockIdx.x * blockDim.x + threadIdx.x;
    const size_t stride = (size_t)gridDim.x * blockDim.x;
    for (; i < n_grp; i += stride) {
        float4 a = src[2 * i];
        float4 b = src[2 * i + 1];
        __half2 h0 = __floats2half2_rn(a.x, a.y);
        __half2 h1 = __floats2half2_rn(a.z, a.w);
        __half2 h2 = __floats2half2_rn(b.x, b.y);
        __half2 h3 = __floats2half2_rn(b.z, b.w);
        uint4 o;
        o.x = *reinterpret_cast<unsigned*>(&h0);
        o.y = *reinterpret_cast<unsigned*>(&h1);
        o.z = *reinterpret_cast<unsigned*>(&h2);
        o.w = *reinterpret_cast<unsigned*>(&h3);
        g_emb_h[i] = o;
    }
}

// ---------------- kernel 2: walk loss + finalize ----------------

// half2 dot of two 8-byte slices, fp16 accumulate, f32 fold
__device__ __forceinline__ float hdot(uint2 a, uint2 b) {
    __half2 a0 = *reinterpret_cast<__half2*>(&a.x);
    __half2 a1 = *reinterpret_cast<__half2*>(&a.y);
    __half2 b0 = *reinterpret_cast<__half2*>(&b.x);
    __half2 b1 = *reinterpret_cast<__half2*>(&b.y);
    __half2 p = __hmul2(a0, b0);
    p = __hfma2(a1, b1, p);
    return __low2float(p) + __high2float(p);
}

__device__ __forceinline__ int load_idx(const int* __restrict__ pos_rw,
                                        const int* __restrict__ neg_rw,
                                        int w, int n_pos, int total, int lane) {
    if (w >= total) return 0;
    const int* rw = (w < n_pos) ? pos_rw + (size_t)w * 7
                                : neg_rw + (size_t)(w - n_pos) * 7;
    return (lane < 7) ? rw[lane] : 0;
}

__device__ __forceinline__ void issue_gather(int my, int lane, uint2* r) {
    const uint2* e = reinterpret_cast<const uint2*>(g_emb_h);
    #pragma unroll
    for (int k = 0; k < 7; k++) {
        int idx = __shfl_sync(0xffffffffu, my, k);
        r[k] = e[(size_t)idx * 32 + lane];
    }
}

__global__ void __launch_bounds__(256, 4)
walk_fin_kernel(const int* __restrict__ pos_rw,
                const int* __restrict__ neg_rw,
                int n_pos, int n_neg, float* __restrict__ out)
{
    __shared__ double sred[2][8];

    const int lane  = threadIdx.x & 31;
    const int wl    = threadIdx.x >> 5;
    const int gw    = (blockIdx.x * blockDim.x + threadIdx.x) >> 5;
    const int W     = (gridDim.x * blockDim.x) >> 5;
    const int total = n_pos + n_neg;

    // one dot-sum lands on each of lanes {0,4,8,16,20,24}
    const bool rep_lane = ((0x01110111u >> lane) & 1u) != 0u;

    float accp = 0.0f, accn = 0.0f;

    int my = load_idx(pos_rw, neg_rw, gw, n_pos, total, lane);
    uint2 r[7];
    issue_gather(my, lane, r);

    for (int w = gw; w < total; w += W) {
        // pipeline next walk's indices + gathers
        int my_n = load_idx(pos_rw, neg_rw, w + W, n_pos, total, lane);
        uint2 rn[7];
        issue_gather(my_n, lane, rn);

        // per-lane partials for the 6 dots (fp16 fma, f32 fold)
        float p1 = hdot(r[0], r[1]);
        float p2 = hdot(r[0], r[2]);
        float p3 = hdot(r[0], r[3]);
        float p4 = hdot(r[0], r[4]);
        float p5 = hdot(r[0], r[5]);
        float p6 = hdot(r[0], r[6]);

        // ---- packed reduction ladder: 13 SHFL + 13 FADD + 5 SEL ----
        p1 += __shfl_xor_sync(0xffffffffu, p1, 16);
        p2 += __shfl_xor_sync(0xffffffffu, p2, 16);
        p3 += __shfl_xor_sync(0xffffffffu, p3, 16);
        p4 += __shfl_xor_sync(0xffffffffu, p4, 16);
        p5 += __shfl_xor_sync(0xffffffffu, p5, 16);
        p6 += __shfl_xor_sync(0xffffffffu, p6, 16);
        // half-warps: lo keeps odd-numbered, hi keeps even partner
        float u1 = (lane < 16) ? p1 : p2;
        float u2 = (lane < 16) ? p3 : p4;
        float u3 = (lane < 16) ? p5 : p6;
        u1 += __shfl_xor_sync(0xffffffffu, u1, 8);
        u2 += __shfl_xor_sync(0xffffffffu, u2, 8);
        u3 += __shfl_xor_sync(0xffffffffu, u3, 8);
        float va = (lane & 8) ? u2 : u1;
        float vb = u3;
        va += __shfl_xor_sync(0xffffffffu, va, 4);
        vb += __shfl_xor_sync(0xffffffffu, vb, 4);
        float wv = (lane & 4) ? vb : va;
        wv += __shfl_xor_sync(0xffffffffu, wv, 2);
        wv += __shfl_xor_sync(0xffffffffu, wv, 1);
        // lanes 0-3:d1  4-7:d5  8-11:d3  12-15:d5'  16-19:d2  20-23:d6
        // 24-27:d4  28-31:d6'   (every lane holds a genuine dot value)

        // ---- loss term, computed warp-wide, accumulated on rep lanes ----
        float e   = __expf(-wv);
        float sig = __frcp_rn(1.0f + e);          // == 1.0f/(1.0f+e), IEEE RN
        float om  = 1.0f - sig;
        const bool is_pos = (w < n_pos);
        float s   = is_pos ? sig : om;
        float arg = s + 1e-15f;
        float term = -__logf(arg);

        if (rep_lane) {
            if (is_pos) accp += term;
            else        accn += term;
        }

        my = my_n;
        #pragma unroll
        for (int k = 0; k < 7; k++) r[k] = rn[k];
    }

    // warp-reduce the per-lane accumulators
    #pragma unroll
    for (int d = 16; d > 0; d >>= 1) {
        accp += __shfl_xor_sync(0xffffffffu, accp, d);
        accn += __shfl_xor_sync(0xffffffffu, accn, d);
    }
    if (lane == 0) { sred[0][wl] = (double)accp; sred[1][wl] = (double)accn; }
    __syncthreads();

    if (threadIdx.x == 0) {
        double p = 0.0, n = 0.0;
        #pragma unroll
        for (int k = 0; k < 8; k++) { p += sred[0][k]; n += sred[1][k]; }
        atomicAdd(&g_acc[0], p);
        atomicAdd(&g_acc[1], n);
        __threadfence();
        unsigned ticket = atomicInc(&g_done, gridDim.x - 1);
        if (ticket == gridDim.x - 1) {
            double pos_loss = g_acc[0] / ((double)n_pos * 6.0);
            double neg_loss = g_acc[1] / ((double)n_neg * 6.0);
            out[0] = (float)(pos_loss + neg_loss);
        }
    }
}

extern "C" void kernel_launch(void* const* d_in, const int* in_sizes, int n_in,
                              void* d_out, int out_size)
{
    const float* emb    = (const float*)d_in[0];
    const int*   pos_rw = (const int*)d_in[1];
    const int*   neg_rw = (const int*)d_in[2];

    const int n_pos = in_sizes[1] / 7;   // 81920
    const int n_neg = in_sizes[2] / 7;   // 409600

    convert_zero_kernel<<<592, 256>>>(emb);
    // 592 CTAs x 8 warps = 4736 warps (exactly 4 CTAs/SM, one wave)
    walk_fin_kernel<<<592, 256>>>(pos_rw, neg_rw, n_pos, n_neg, (float*)d_out);
}